// round 10
// baseline (speedup 1.0000x reference)
#include <cuda_runtime.h>
#include <cuda.h>
#include <cuda_bf16.h>
#include <math.h>
#include <stdint.h>

#define Bc 8
#define Nn 4096
#define Dd 768
#define Hh 12
#define dh 64
#define Mrows (Bc*Nn)      /* 32768 */
#define QKVC  (3*Dd)       /* 2304  */
#define GK    Dd           /* GEMM K = 768 */
#define NSPLIT 8

// ---------------- scratch (device globals; allocation-free rule) -----------
__device__ float g_qkv[(size_t)Mrows * QKVC];          // 302 MB
__device__ float g_attn[Bc*Hh*dh*dh];                  // 1.5 MB
__device__ float g_part[(size_t)Bc*Hh*NSPLIT*dh*dh];   // 12.6 MB
__device__ float g_psq[Bc*Hh*NSPLIT*2*dh];             // 0.4 MB
// Tiled bf16 operands: [rtile256][kchunk32][256r x 32k] 16KB blocks
__device__ __align__(256) __nv_bfloat16 g_xh[(size_t)Mrows*Dd],  g_xl[(size_t)Mrows*Dd];
__device__ __align__(256) __nv_bfloat16 g_wh[(size_t)QKVC*Dd],   g_wl[(size_t)QKVC*Dd];
__device__ __align__(256) __nv_bfloat16 g_woh[(size_t)Dd*Dd],    g_wol[(size_t)Dd*Dd];
__device__ __align__(256) __nv_bfloat16 g_oh[(size_t)Mrows*Dd],  g_ol[(size_t)Mrows*Dd];
// tensormaps: [0..3]=GEMM1 {Ah,Al,Bh,Bl}, [4..7]=GEMM2
__device__ __align__(128) CUtensorMap g_tmaps[8];

// ---------------- arch feature gate -----------------------------------------
#if defined(__CUDA_ARCH_FEAT_SM103_ALL) || defined(__CUDA_ARCH_FEAT_SM100_ALL) || defined(__CUDA_ARCH_FEAT_SM101_ALL)
#define HAS_TCG 1
#else
#define HAS_TCG 0
#endif

// ---------------- common helpers --------------------------------------------
__device__ __forceinline__ uint32_t smem_u32(const void* p){
    uint32_t a;
    asm("{ .reg .u64 t; cvta.to.shared.u64 t, %1; cvt.u32.u64 %0, t; }" : "=r"(a) : "l"(p));
    return a;
}
// element offset of (row r, col k) in tiled layout, K columns total
__device__ __forceinline__ size_t tiled_off(int r, int k, int K){
    return ((size_t)((r >> 8) * (K >> 5) + (k >> 5)) << 13) + ((r & 255) << 5) + (k & 31);
}

// ---------------- GEMM tile geometry ----------------------------------------
#define MT 256
#define NT 256
#define KCH 32
#define NCH (GK/KCH)            /* 24 */
#define NSTAGE 3
// per-stage region offsets (bytes from stage base); A/B halves at +0/+8192
#define OAH 0
#define OAL 16384
#define OBH 32768
#define OBL 49152
#define STAGE_BYTES 65536
#define SM_TILE0 1024
#define GEMM_SMEM (SM_TILE0 + NSTAGE*STAGE_BYTES) /* 197632 */

#if HAS_TCG
// ---------------- tcgen05 / TMA helpers (arch-specific pass only) -----------
__device__ __forceinline__ uint32_t elect1(){
    uint32_t p;
    asm volatile("{\n\t.reg .pred p;\n\telect.sync _|p, 0xFFFFFFFF;\n\tselp.b32 %0, 1, 0, p;\n\t}" : "=r"(p));
    return p;
}
__device__ __forceinline__ uint32_t ctarank(){
    uint32_t r;
    asm("mov.u32 %0, %%cluster_ctarank;" : "=r"(r));
    return r;
}
// SW64 descriptor: layout=4, version=1, SBO=32 (512B = 8 rows x 64B), LBO=1
static constexpr uint64_t DESC_BASE_SW64 =
    (uint64_t(4) << 61) | (uint64_t(1) << 46) | (uint64_t(32) << 32) | (uint64_t(1) << 16);
#define MK64(a) (DESC_BASE_SW64 | ((uint64_t)((a) >> 4) & 0x3FFF))
// idesc: F32 accum, BF16 a/b, M=128, N=256
#define GEMM_IDESC 0x8400490u

__device__ __forceinline__ void mma_bf16_ss(uint32_t d, uint64_t a, uint64_t b, uint32_t en){
    asm volatile(
        "{\n\t.reg .pred p;\n\tsetp.ne.u32 p, %3, 0;\n\t"
        "tcgen05.mma.cta_group::1.kind::f16 [%0], %1, %2, %4, {%5,%5,%5,%5}, p;\n\t}"
        :: "r"(d), "l"(a), "l"(b), "r"(en), "r"(GEMM_IDESC), "r"(0u) : "memory");
}
__device__ __forceinline__ void tc_commit(uint32_t mbar){
    asm volatile("tcgen05.commit.cta_group::1.mbarrier::arrive::one.shared::cluster.b64 [%0];"
                 :: "r"(mbar) : "memory");
}
__device__ __forceinline__ void tc_commit_mc(uint32_t mbar, uint16_t mask){
    asm volatile("tcgen05.commit.cta_group::1.mbarrier::arrive::one.shared::cluster.multicast::cluster.b64 [%0], %1;"
                 :: "r"(mbar), "h"(mask) : "memory");
}
__device__ __forceinline__ void mbar_init(uint32_t mbar, uint32_t cnt){
    asm volatile("mbarrier.init.shared.b64 [%0], %1;" :: "r"(mbar), "r"(cnt) : "memory");
}
__device__ __forceinline__ void mbar_wait(uint32_t mbar, uint32_t parity){
    asm volatile(
        "{\n\t.reg .pred P;\n\tWL_%=:\n\t"
        "mbarrier.try_wait.parity.acquire.cta.shared::cta.b64 P, [%0], %1, 0x989680;\n\t"
        "@P bra.uni WD_%=;\n\tbra.uni WL_%=;\n\tWD_%=:\n\t}"
        :: "r"(mbar), "r"(parity) : "memory");
}
__device__ __forceinline__ void mbar_wait_rlx(uint32_t mbar, uint32_t parity){
    asm volatile(
        "{\n\t.reg .pred P;\n\tWL_%=:\n\t"
        "mbarrier.try_wait.parity.relaxed.cta.shared::cta.b64 P, [%0], %1, 0x989680;\n\t"
        "@P bra.uni WD_%=;\n\tbra.uni WL_%=;\n\tWD_%=:\n\t}"
        :: "r"(mbar), "r"(parity) : "memory");
}
#define EXPECT_TX(mbar, bytes) \
    asm volatile("mbarrier.arrive.expect_tx.shared.b64 _, [%0], %1;" \
                 :: "r"(mbar), "r"((uint32_t)(bytes)) : "memory")
#define TMA2D(smem, map, x, y, mbar) \
    asm volatile("cp.async.bulk.tensor.2d.shared::cta.global.tile.mbarrier::complete_tx::bytes " \
                 "[%0], [%1, {%2, %3}], [%4];" \
                 :: "r"((uint32_t)(smem)), "l"(map), "r"((int)(x)), "r"((int)(y)), \
                    "r"((uint32_t)(mbar)) : "memory")
#define TMA2D_MC(smem, map, x, y, mbar, mask) \
    asm volatile("cp.async.bulk.tensor.2d.shared::cluster.global.tile.mbarrier::complete_tx::bytes.multicast::cluster " \
                 "[%0], [%1, {%2, %3}], [%4], %5;" \
                 :: "r"((uint32_t)(smem)), "l"(map), "r"((int)(x)), "r"((int)(y)), \
                    "r"((uint32_t)(mbar)), "h"((uint16_t)(mask)) : "memory")
#define TMA_PF2D(map, x, y) \
    asm volatile("cp.async.bulk.prefetch.tensor.2d.L2.global.tile [%0, {%1, %2}];" \
                 :: "l"(map), "r"((int)(x)), "r"((int)(y)) : "memory")
#define CLUSTER_SYNC() do { \
    asm volatile("barrier.cluster.arrive.aligned;" ::: "memory"); \
    asm volatile("barrier.cluster.wait.aligned;" ::: "memory"); \
} while(0)

#define FENCE_ASYNC()  asm volatile("fence.proxy.async.shared::cta;" ::: "memory")
#define TC_FENCE_AFTER()  asm volatile("tcgen05.fence::after_thread_sync;" ::: "memory")
#define TC_FENCE_BEFORE() asm volatile("tcgen05.fence::before_thread_sync;" ::: "memory")
#define TC_WAIT_LD() asm volatile("tcgen05.wait::ld.sync.aligned;" ::: "memory")

#define LDTM32(r, addr) \
    asm volatile( \
        "tcgen05.ld.sync.aligned.32x32b.x32.b32 " \
        "{%0, %1, %2, %3, %4, %5, %6, %7, " \
        " %8, %9, %10, %11, %12, %13, %14, %15, " \
        " %16, %17, %18, %19, %20, %21, %22, %23, " \
        " %24, %25, %26, %27, %28, %29, %30, %31}, [%32];" \
        : "=r"((r)[0]),  "=r"((r)[1]),  "=r"((r)[2]),  "=r"((r)[3]), \
          "=r"((r)[4]),  "=r"((r)[5]),  "=r"((r)[6]),  "=r"((r)[7]), \
          "=r"((r)[8]),  "=r"((r)[9]),  "=r"((r)[10]), "=r"((r)[11]), \
          "=r"((r)[12]), "=r"((r)[13]), "=r"((r)[14]), "=r"((r)[15]), \
          "=r"((r)[16]), "=r"((r)[17]), "=r"((r)[18]), "=r"((r)[19]), \
          "=r"((r)[20]), "=r"((r)[21]), "=r"((r)[22]), "=r"((r)[23]), \
          "=r"((r)[24]), "=r"((r)[25]), "=r"((r)[26]), "=r"((r)[27]), \
          "=r"((r)[28]), "=r"((r)[29]), "=r"((r)[30]), "=r"((r)[31]) \
        : "r"(addr))
#endif  // HAS_TCG

// smem control offsets
#define MB_FULL(s)  (8  + (s)*8)     /* full[s]:  data ready (count 1 + tx) */
#define MB_EMPTY(s) (40 + (s)*8)     /* empty[s]: stage free (count 2)      */
#define MB_DONE     72               /* final MMA drain (count 1)           */

// ---------------------------------------------------------------------------
// 3-pass bf16 (hi/lo split) GEMM on TILED operands via TMA + B-multicast
// + L2 tensor prefetch NSTAGE chunks ahead.
// ---------------------------------------------------------------------------
__global__ __launch_bounds__(256) __cluster_dims__(1, 2, 1)
void gemm_bf16_3p(
    const CUtensorMap* __restrict__ tmaps,   // [Ah, Al, Bh, Bl]
    const __nv_bfloat16* __restrict__ Ah, const __nv_bfloat16* __restrict__ Al,
    const __nv_bfloat16* __restrict__ Bh, const __nv_bfloat16* __restrict__ Bl,
    float* __restrict__ C, int Ntot, const float* __restrict__ bias)
{
    const int tid = threadIdx.x;
    const int row0 = blockIdx.y * MT;
    const int col0 = blockIdx.x * NT;

#if HAS_TCG
    extern __shared__ char smem[];
    const uint32_t sbase = smem_u32(smem);
    const int wid = tid >> 5;
    const int lane = tid & 31;
    const uint32_t rank = ctarank();

    if (wid == 0) {
        asm volatile("tcgen05.alloc.cta_group::1.sync.aligned.shared::cta.b32 [%0], %1;"
                     :: "r"(sbase), "r"(512u) : "memory");
    }
    if (tid == 0) {
        #pragma unroll
        for (int s = 0; s < NSTAGE; s++) {
            mbar_init(sbase + MB_FULL(s), 1);    // producer's expect_tx arrival
            mbar_init(sbase + MB_EMPTY(s), 2);   // both CTAs' MMA commits
        }
        mbar_init(sbase + MB_DONE, 1);
    }
    __syncthreads();
    uint32_t tmem;
    asm volatile("ld.shared.b32 %0, [%1];" : "=r"(tmem) : "r"(sbase));
    if (wid == 0)
        asm volatile("tcgen05.relinquish_alloc_permit.cta_group::1.sync.aligned;");

    // all mbarriers must be visible cluster-wide before any multicast TMA
    CLUSTER_SYNC();

    uint32_t leader = 0, producer = 0;
    if (wid == 0) leader = elect1();
    if (wid == 1) producer = elect1();

    if (producer) {
        const int abase = blockIdx.y * NCH;
        const int bbase = blockIdx.x * NCH;
        // prologue L2 prefetch: first 2*NSTAGE chunks (each CTA prefetches
        // exactly the halves it will later TMA)
        #pragma unroll
        for (int pc = 0; pc < 2*NSTAGE && pc < NCH; pc++) {
            TMA_PF2D(tmaps + 0, 0, (abase + pc) * 256);
            TMA_PF2D(tmaps + 1, 0, (abase + pc) * 256);
            TMA_PF2D(tmaps + 2, 0, (bbase + pc) * 256 + (int)rank * 128);
            TMA_PF2D(tmaps + 3, 0, (bbase + pc) * 256 + (int)rank * 128);
        }
        for (int ch = 0; ch < NCH; ch++) {
            const int st = ch % NSTAGE;
            const uint32_t sb = sbase + SM_TILE0 + st*STAGE_BYTES;
            if (ch >= NSTAGE)
                mbar_wait_rlx(sbase + MB_EMPTY(st), ((ch - NSTAGE) / NSTAGE) & 1);
            EXPECT_TX(sbase + MB_FULL(st), 65536u);
            const int ya = (abase + ch) * 256;
            TMA2D(sb + OAH, tmaps + 0, 0, ya, sbase + MB_FULL(st));
            TMA2D(sb + OAL, tmaps + 1, 0, ya, sbase + MB_FULL(st));
            const int yb = (bbase + ch) * 256 + (int)rank * 128;
            TMA2D_MC(sb + OBH + rank*8192, tmaps + 2, 0, yb, sbase + MB_FULL(st), 3);
            TMA2D_MC(sb + OBL + rank*8192, tmaps + 3, 0, yb, sbase + MB_FULL(st), 3);
            // L2 prefetch 2*NSTAGE chunks ahead
            const int pf = ch + 2*NSTAGE;
            if (pf < NCH) {
                TMA_PF2D(tmaps + 0, 0, (abase + pf) * 256);
                TMA_PF2D(tmaps + 1, 0, (abase + pf) * 256);
                TMA_PF2D(tmaps + 2, 0, (bbase + pf) * 256 + (int)rank * 128);
                TMA_PF2D(tmaps + 3, 0, (bbase + pf) * 256 + (int)rank * 128);
            }
        }
    }

    if (leader) {
        uint32_t first = 0;
        const uint32_t tm0 = tmem, tm1 = tmem + 256;
        for (int ch = 0; ch < NCH; ch++) {
            const int st = ch % NSTAGE;
            mbar_wait(sbase + MB_FULL(st), (ch / NSTAGE) & 1);
            const uint32_t sb = sbase + SM_TILE0 + st*STAGE_BYTES;
            const uint64_t dA0h = MK64(sb + OAH), dA1h = MK64(sb + OAH + 8192);
            const uint64_t dA0l = MK64(sb + OAL), dA1l = MK64(sb + OAL + 8192);
            const uint64_t dBh  = MK64(sb + OBH), dBl  = MK64(sb + OBL);
            #pragma unroll
            for (int k = 0; k < 2; k++) {
                const uint64_t o = k*2;
                mma_bf16_ss(tm0, dA0h + o, dBh + o, first);
                mma_bf16_ss(tm1, dA1h + o, dBh + o, first);
                first = 1;
                mma_bf16_ss(tm0, dA0h + o, dBl + o, 1);
                mma_bf16_ss(tm1, dA1h + o, dBl + o, 1);
                mma_bf16_ss(tm0, dA0l + o, dBh + o, 1);
                mma_bf16_ss(tm1, dA1l + o, dBh + o, 1);
            }
            tc_commit_mc(sbase + MB_EMPTY(st), 3);   // arm both CTAs' empty
        }
        tc_commit(sbase + MB_DONE);
    }

    // ---- all threads: wait for full MMA drain ----
    mbar_wait(sbase + MB_DONE, 0);
    TC_FENCE_AFTER();

    // ---- epilogue: warps 0-3 -> D0 rows, warps 4-7 -> D1 rows ----
    {
        const int mh = wid >> 2;
        const int r = row0 + mh*128 + (wid & 3)*32 + lane;
        const uint32_t tb = tmem + mh*256;
        float* crow = C + (size_t)r * Ntot;
        #pragma unroll
        for (int chk = 0; chk < 8; chk++) {
            uint32_t regs[32];
            LDTM32(regs, tb + chk*32);
            TC_WAIT_LD();
            const int c0 = col0 + chk*32;
            #pragma unroll
            for (int j = 0; j < 32; j += 4) {
                float4 v;
                v.x = __uint_as_float(regs[j+0]);
                v.y = __uint_as_float(regs[j+1]);
                v.z = __uint_as_float(regs[j+2]);
                v.w = __uint_as_float(regs[j+3]);
                if (bias) {
                    v.x += bias[c0+j+0]; v.y += bias[c0+j+1];
                    v.z += bias[c0+j+2]; v.w += bias[c0+j+3];
                }
                *(float4*)(crow + c0 + j) = v;
            }
        }
        TC_FENCE_BEFORE();
    }
    __syncthreads();
    if (tid == 0) {
        #pragma unroll
        for (int s = 0; s < NSTAGE; s++) {
            asm volatile("mbarrier.inval.shared.b64 [%0];" :: "r"(sbase + MB_FULL(s)) : "memory");
            asm volatile("mbarrier.inval.shared.b64 [%0];" :: "r"(sbase + MB_EMPTY(s)) : "memory");
        }
        asm volatile("mbarrier.inval.shared.b64 [%0];" :: "r"(sbase + MB_DONE) : "memory");
    }
    __syncthreads();
    if (wid == 0) {
        asm volatile("tcgen05.dealloc.cta_group::1.sync.aligned.b32 %0, %1;"
                     :: "r"(tmem), "r"(512u));
    }
    // no CTA may exit while peer multicast could target it
    CLUSTER_SYNC();

#else
    // ---- correctness-only fallback (dead code on sm_103a cubin) ----
    (void)tmaps;
    for (int idx = tid; idx < MT*NT; idx += 256) {
        const int r = row0 + idx / NT;
        const int c = col0 + idx % NT;
        float s = bias ? bias[c] : 0.f;
        for (int k = 0; k < GK; k++) {
            float av = __bfloat162float(Ah[tiled_off(r, k, GK)]) +
                       __bfloat162float(Al[tiled_off(r, k, GK)]);
            float bv = __bfloat162float(Bh[tiled_off(c, k, GK)]) +
                       __bfloat162float(Bl[tiled_off(c, k, GK)]);
            s = fmaf(av, bv, s);
        }
        C[(size_t)r * Ntot + c] = s;
    }
#endif
}

// ---------------------------------------------------------------------------
// fp32 [rows x 768] -> bf16 hi/lo in TILED layout
// ---------------------------------------------------------------------------
__global__ __launch_bounds__(256) void split_kernel(
    const float* __restrict__ in, __nv_bfloat16* __restrict__ h,
    __nv_bfloat16* __restrict__ l, int rows)
{
    const size_t i = (size_t)blockIdx.x * blockDim.x + threadIdx.x;
    if (i >= (size_t)rows * (Dd/4)) return;
    const int r  = (int)(i / (Dd/4));
    const int kq = (int)(i % (Dd/4)) * 4;
    float4 v = *(const float4*)(in + (size_t)r * Dd + kq);
    __nv_bfloat16 h0 = __float2bfloat16(v.x), h1 = __float2bfloat16(v.y);
    __nv_bfloat16 h2 = __float2bfloat16(v.z), h3 = __float2bfloat16(v.w);
    __nv_bfloat16 l0 = __float2bfloat16(v.x - __bfloat162float(h0));
    __nv_bfloat16 l1 = __float2bfloat16(v.y - __bfloat162float(h1));
    __nv_bfloat16 l2 = __float2bfloat16(v.z - __bfloat162float(h2));
    __nv_bfloat16 l3 = __float2bfloat16(v.w - __bfloat162float(h3));
    const size_t off = tiled_off(r, kq, Dd);
    *(__nv_bfloat162*)(h + off)     = __halves2bfloat162(h0, h1);
    *(__nv_bfloat162*)(h + off + 2) = __halves2bfloat162(h2, h3);
    *(__nv_bfloat162*)(l + off)     = __halves2bfloat162(l0, l1);
    *(__nv_bfloat162*)(l + off + 2) = __halves2bfloat162(l2, l3);
}

// ---------------------------------------------------------------------------
// W [K,N] fp32 -> transposed bf16 hi/lo, TILED [N rows x K cols]
// ---------------------------------------------------------------------------
__global__ __launch_bounds__(256) void transpose_split(
    const float* __restrict__ W, __nv_bfloat16* __restrict__ h,
    __nv_bfloat16* __restrict__ l, int K, int N)
{
    __shared__ float t[32][33];
    const int n0 = blockIdx.x * 32, k0 = blockIdx.y * 32;
    const int tx = threadIdx.x & 31, ty = threadIdx.x >> 5;
    #pragma unroll
    for (int i = ty; i < 32; i += 8)
        t[i][tx] = W[(size_t)(k0 + i) * N + n0 + tx];
    __syncthreads();
    #pragma unroll
    for (int i = ty; i < 32; i += 8) {
        float v = t[tx][i];
        __nv_bfloat16 hv = __float2bfloat16(v);
        __nv_bfloat16 lv = __float2bfloat16(v - __bfloat162float(hv));
        const size_t off = tiled_off(n0 + i, k0 + tx, K);
        h[off] = hv;
        l[off] = lv;
    }
}

// ---------------------------------------------------------------------------
// attn part 1: raw cross-cov partials + ssq partials over an N-slice of 512.
// ---------------------------------------------------------------------------
__global__ __launch_bounds__(256) void attn_part(void)
{
    const int bh = blockIdx.x;
    const int sl = blockIdx.y;
    const int b  = bh / Hh, h = bh % Hh;
    const int tid = threadIdx.x;
    const int tx = tid & 15, ty = tid >> 4;

    __shared__ float Qs[64][68];
    __shared__ float Ks[64][68];
    __shared__ float ps[256];

    const size_t rowbase = (size_t)b * Nn + sl * (Nn / NSPLIT);
    const int qoff = h * dh;
    const int koff = Dd + h * dh;

    float acc[4][4];
    #pragma unroll
    for (int i = 0; i < 4; i++)
        #pragma unroll
        for (int j = 0; j < 4; j++) acc[i][j] = 0.f;
    float pssq = 0.f;

    const int lr = tid >> 4;
    const int lc = (tid & 15) << 2;
    const int scol  = tid & 127;
    const int shalf = (tid >> 7) * 32;

    for (int n0 = 0; n0 < Nn / NSPLIT; n0 += 64) {
        #pragma unroll
        for (int pp = 0; pp < 64; pp += 16) {
            const size_t grow = (rowbase + n0 + pp + lr) * QKVC;
            *(float4*)&Qs[pp + lr][lc] = *(const float4*)(g_qkv + grow + qoff + lc);
            *(float4*)&Ks[pp + lr][lc] = *(const float4*)(g_qkv + grow + koff + lc);
        }
        __syncthreads();
        #pragma unroll 4
        for (int n = 0; n < 64; n++) {
            float rq[4], rk[4];
            *(float4*)rq = *(const float4*)&Qs[n][tx * 4];
            *(float4*)rk = *(const float4*)&Ks[n][ty * 4];
            #pragma unroll
            for (int i = 0; i < 4; i++)
                #pragma unroll
                for (int j = 0; j < 4; j++)
                    acc[i][j] = fmaf(rk[i], rq[j], acc[i][j]);
        }
        {
            const float* colp = (scol < 64) ? &Qs[0][scol] : &Ks[0][scol - 64];
            #pragma unroll
            for (int n = 0; n < 32; n++) {
                const float v = colp[(size_t)(shalf + n) * 68];
                pssq = fmaf(v, v, pssq);
            }
        }
        __syncthreads();
    }

    ps[tid] = pssq;
    __syncthreads();
    if (tid < 128)
        g_psq[(bh * NSPLIT + sl) * 128 + tid] = ps[tid] + ps[tid + 128];

    float* op = g_part + (size_t)(bh * NSPLIT + sl) * 4096;
    #pragma unroll
    for (int i = 0; i < 4; i++)
        #pragma unroll
        for (int j = 0; j < 4; j++)
            op[(ty * 4 + i) * 64 + tx * 4 + j] = acc[i][j];
}

// ---------------------------------------------------------------------------
// attn part 2: reduce partials, norms, temperature, softmax. grid 96.
// ---------------------------------------------------------------------------
__global__ __launch_bounds__(256) void attn_final(const float* __restrict__ temp)
{
    const int bh = blockIdx.x;
    const int h  = bh % Hh;
    const int tid = threadIdx.x;

    __shared__ float Qs[64][65];
    __shared__ float normQ[64], normK[64];

    if (tid < 128) {
        float s = 0.f;
        #pragma unroll
        for (int sl = 0; sl < NSPLIT; sl++)
            s += g_psq[(bh * NSPLIT + sl) * 128 + tid];
        const float nv = fmaxf(sqrtf(s), 1e-12f);
        if (tid < 64) normQ[tid] = nv; else normK[tid - 64] = nv;
    }
    __syncthreads();

    const float tv = temp[h];
    const float* pp = g_part + (size_t)bh * NSPLIT * 4096;
    #pragma unroll
    for (int e = 0; e < 16; e++) {
        const int idx = e * 256 + tid;
        float s = 0.f;
        #pragma unroll
        for (int sl = 0; sl < NSPLIT; sl++)
            s += pp[sl * 4096 + idx];
        const int p = idx >> 6, q = idx & 63;
        Qs[p][q] = s * tv / (normK[p] * normQ[q]);
    }
    __syncthreads();

    if (tid < 64) {
        const int p = tid;
        float m = -1e30f;
        for (int q = 0; q < 64; q++) m = fmaxf(m, Qs[p][q]);
        float s = 0.f;
        for (int q = 0; q < 64; q++) s += expf(Qs[p][q] - m);
        const float inv = 1.f / s;
        float* op = g_attn + (size_t)bh * 4096 + p * 64;
        for (int q = 0; q < 64; q++) op[q] = expf(Qs[p][q] - m) * inv;
    }
}

// ---------------------------------------------------------------------------
// out[b,h,n,q] = sum_p v[n,p] attn[p,q]  -> bf16 hi/lo in TILED layout
// ---------------------------------------------------------------------------
__global__ __launch_bounds__(256) void av_kernel()
{
    const int bh = blockIdx.x;
    const int nt = blockIdx.y;
    const int b  = bh / Hh, h = bh % Hh;
    const int tid = threadIdx.x;
    const int tx = tid & 15, ty = tid >> 4;

    __shared__ float At[64][68];
    __shared__ float Vs[64][68];

    {
        const float* ap = g_attn + (size_t)bh * 4096;
        #pragma unroll
        for (int pp = 0; pp < 4; pp++) {
            const int idx = pp * 1024 + tid * 4;
            *(float4*)&At[idx >> 6][idx & 63] = *(const float4*)(ap + idx);
        }
    }
    const int lr = tid >> 4, lc = (tid & 15) << 2;
    const int voff = 2 * Dd + h * dh;
    const size_t rowbase = (size_t)b * Nn + nt * 64;
    #pragma unroll
    for (int pp = 0; pp < 64; pp += 16)
        *(float4*)&Vs[pp + lr][lc] =
            *(const float4*)(g_qkv + (rowbase + pp + lr) * QKVC + voff + lc);
    __syncthreads();

    float acc[4][4];
    #pragma unroll
    for (int i = 0; i < 4; i++)
        #pragma unroll
        for (int j = 0; j < 4; j++) acc[i][j] = 0.f;

    #pragma unroll 8
    for (int p = 0; p < 64; p++) {
        float ra[4];
        *(float4*)ra = *(const float4*)&At[p][tx * 4];
        float rv[4];
        #pragma unroll
        for (int i = 0; i < 4; i++) rv[i] = Vs[ty * 4 + i][p];
        #pragma unroll
        for (int i = 0; i < 4; i++)
            #pragma unroll
            for (int j = 0; j < 4; j++)
                acc[i][j] = fmaf(rv[i], ra[j], acc[i][j]);
    }

    #pragma unroll
    for (int i = 0; i < 4; i++) {
        const int r = (int)rowbase + ty * 4 + i;
        const int col = h * dh + tx * 4;
        const size_t off = tiled_off(r, col, Dd);
        __nv_bfloat16 hv[4], lv[4];
        #pragma unroll
        for (int j = 0; j < 4; j++) {
            hv[j] = __float2bfloat16(acc[i][j]);
            lv[j] = __float2bfloat16(acc[i][j] - __bfloat162float(hv[j]));
        }
        *(__nv_bfloat162*)(g_oh + off)     = __halves2bfloat162(hv[0], hv[1]);
        *(__nv_bfloat162*)(g_oh + off + 2) = __halves2bfloat162(hv[2], hv[3]);
        *(__nv_bfloat162*)(g_ol + off)     = __halves2bfloat162(lv[0], lv[1]);
        *(__nv_bfloat162*)(g_ol + off + 2) = __halves2bfloat162(lv[2], lv[3]);
    }
}

// ---------------------------------------------------------------------------
// host: tensormap construction via driver entry point (no -lcuda needed)
// ---------------------------------------------------------------------------
typedef CUresult (*EncodeTiledFn)(
    CUtensorMap*, CUtensorMapDataType, cuuint32_t, void*,
    const cuuint64_t*, const cuuint64_t*, const cuuint32_t*, const cuuint32_t*,
    CUtensorMapInterleave, CUtensorMapSwizzle, CUtensorMapL2promotion,
    CUtensorMapFloatOOBfill);

static void encode_map(EncodeTiledFn enc, CUtensorMap* m, void* base,
                       unsigned long long nrows, unsigned boxrows)
{
    cuuint64_t dims[2]    = {32ull, nrows};
    cuuint64_t strides[1] = {64ull};          // bytes per row
    cuuint32_t box[2]     = {32u, boxrows};
    cuuint32_t estr[2]    = {1u, 1u};
    enc(m, CU_TENSOR_MAP_DATA_TYPE_BFLOAT16, 2, base, dims, strides, box, estr,
        CU_TENSOR_MAP_INTERLEAVE_NONE, CU_TENSOR_MAP_SWIZZLE_64B,
        CU_TENSOR_MAP_L2_PROMOTION_L2_128B, CU_TENSOR_MAP_FLOAT_OOB_FILL_NONE);
}

extern "C" void kernel_launch(void* const* d_in, const int* in_sizes, int n_in,
                              void* d_out, int out_size)
{
    const float* x     = (const float*)d_in[0];
    const float* Wqkv  = (const float*)d_in[1];
    const float* temp  = (const float*)d_in[2];
    const float* Wout  = (const float*)d_in[3];
    const float* bout  = (const float*)d_in[4];
    float* out = (float*)d_out;

    float *qkv;
    __nv_bfloat16 *xh, *xl, *wh, *wl, *woh, *wol, *oh, *ol;
    cudaGetSymbolAddress((void**)&qkv,   g_qkv);
    cudaGetSymbolAddress((void**)&xh,  g_xh);  cudaGetSymbolAddress((void**)&xl,  g_xl);
    cudaGetSymbolAddress((void**)&wh,  g_wh);  cudaGetSymbolAddress((void**)&wl,  g_wl);
    cudaGetSymbolAddress((void**)&woh, g_woh); cudaGetSymbolAddress((void**)&wol, g_wol);
    cudaGetSymbolAddress((void**)&oh,  g_oh);  cudaGetSymbolAddress((void**)&ol,  g_ol);
    CUtensorMap* dmaps;
    cudaGetSymbolAddress((void**)&dmaps, g_tmaps);

    // build tensormaps (static host buffer persists for graph replays)
    static CUtensorMap h_tmaps[8];
    static EncodeTiledFn enc = nullptr;
    if (!enc) {
        void* p = nullptr;
        cudaDriverEntryPointQueryResult st;
        cudaGetDriverEntryPoint("cuTensorMapEncodeTiled", &p, cudaEnableDefault, &st);
        enc = (EncodeTiledFn)p;
    }
    encode_map(enc, &h_tmaps[0], xh,  (unsigned long long)Mrows * Dd / 32, 256);
    encode_map(enc, &h_tmaps[1], xl,  (unsigned long long)Mrows * Dd / 32, 256);
    encode_map(enc, &h_tmaps[2], wh,  (unsigned long long)QKVC  * Dd / 32, 128);
    encode_map(enc, &h_tmaps[3], wl,  (unsigned long long)QKVC  * Dd / 32, 128);
    encode_map(enc, &h_tmaps[4], oh,  (unsigned long long)Mrows * Dd / 32, 256);
    encode_map(enc, &h_tmaps[5], ol,  (unsigned long long)Mrows * Dd / 32, 256);
    encode_map(enc, &h_tmaps[6], woh, (unsigned long long)Dd    * Dd / 32, 128);
    encode_map(enc, &h_tmaps[7], wol, (unsigned long long)Dd    * Dd / 32, 128);
    cudaMemcpyToSymbolAsync(g_tmaps, h_tmaps, sizeof(h_tmaps), 0,
                            cudaMemcpyHostToDevice, 0);

    cudaFuncSetAttribute(gemm_bf16_3p, cudaFuncAttributeMaxDynamicSharedMemorySize, GEMM_SMEM);

    // 1) split inputs to bf16 hi/lo (tiled layouts)
    {
        size_t nthr = (size_t)Mrows * (Dd/4);
        split_kernel<<<(unsigned)((nthr + 255) / 256), 256>>>(x, xh, xl, Mrows);
    }
    transpose_split<<<dim3(QKVC/32, Dd/32), 256>>>(Wqkv, wh, wl, Dd, QKVC);
    transpose_split<<<dim3(Dd/32,  Dd/32), 256>>>(Wout, woh, wol, Dd, Dd);

    // 2) qkv = x @ Wqkv  (tcgen05, TMA + B-multicast + L2 prefetch)
    gemm_bf16_3p<<<dim3(QKVC/NT, Mrows/MT), 256, GEMM_SMEM>>>(
        dmaps + 0, xh, xl, wh, wl, qkv, QKVC, nullptr);

    // 3) fused normalize + cross-covariance + temperature + softmax (split 8x)
    attn_part<<<dim3(Bc * Hh, NSPLIT), 256>>>();
    attn_final<<<dim3(Bc * Hh), 256>>>(temp);

    // 4) out = v @ attn  (writes tiled bf16 hi/lo directly)
    av_kernel<<<dim3(Bc * Hh, Nn / 64), 256>>>();

    // 5) final projection + bias (tcgen05)
    gemm_bf16_3p<<<dim3(Dd/NT, Mrows/MT), 256, GEMM_SMEM>>>(
        dmaps + 4, oh, ol, woh, wol, out, Dd, bout);
}

// round 11
// speedup vs baseline: 1.1792x; 1.1792x over previous
#include <cuda_runtime.h>
#include <cuda.h>
#include <cuda_bf16.h>
#include <math.h>
#include <stdint.h>

#define Bc 8
#define Nn 4096
#define Dd 768
#define Hh 12
#define dh 64
#define Mrows (Bc*Nn)      /* 32768 */
#define QKVC  (3*Dd)       /* 2304  */
#define GK    Dd           /* GEMM K = 768 */
#define NSPLIT 8

// ---------------- scratch (device globals; allocation-free rule) -----------
__device__ float g_qkv[(size_t)Mrows * QKVC];          // 302 MB
__device__ float g_attn[Bc*Hh*dh*dh];                  // 1.5 MB
__device__ float g_part[(size_t)Bc*Hh*NSPLIT*dh*dh];   // 12.6 MB
__device__ float g_psq[Bc*Hh*NSPLIT*2*dh];             // 0.4 MB
__device__ __align__(256) float g_xt[(size_t)Mrows*Dd];     // x rounded to tf32
__device__ __align__(256) float g_wt[(size_t)QKVC*Dd];      // Wqkv^T  [N,K] tf32
__device__ __align__(256) float g_wot[(size_t)Dd*Dd];       // Wout^T  [N,K] tf32
__device__ __align__(256) float g_oattn[(size_t)Mrows*Dd];  // v@attn  tf32
// tensormaps: [0]=x, [1]=WqkvT, [2]=oattn, [3]=WoutT
__device__ __align__(128) CUtensorMap g_tmaps[4];

// ---------------- arch feature gate -----------------------------------------
#if defined(__CUDA_ARCH_FEAT_SM103_ALL) || defined(__CUDA_ARCH_FEAT_SM100_ALL) || defined(__CUDA_ARCH_FEAT_SM101_ALL)
#define HAS_TCG 1
#else
#define HAS_TCG 0
#endif

// ---------------- common helpers --------------------------------------------
__device__ __forceinline__ uint32_t smem_u32(const void* p){
    uint32_t a;
    asm("{ .reg .u64 t; cvta.to.shared.u64 t, %1; cvt.u32.u64 %0, t; }" : "=r"(a) : "l"(p));
    return a;
}
// round fp32 -> tf32 (round-to-nearest; avoids truncation bias in HW)
__device__ __forceinline__ float rna_tf32(float v){
    uint32_t u;
    asm("cvt.rna.tf32.f32 %0, %1;" : "=r"(u) : "f"(v));
    return __uint_as_float(u);
}

// ---------------- GEMM tile geometry ----------------------------------------
#define MT 256
#define NT 256
#define KCH 32                  /* K elems per chunk: 32 fp32 = 128B rows */
#define NCH (GK/KCH)            /* 24 */
#define NSTAGE 3
// per-stage region offsets (bytes from stage base)
#define OA 0                    /* A tile 256x32 fp32 = 32KB (halves at +0/+16K) */
#define OB 32768                /* B tile 256x32 fp32 = 32KB (mc halves +0/+16K) */
#define STAGE_BYTES 65536
#define SM_TILE0 1024
#define GEMM_SMEM (SM_TILE0 + NSTAGE*STAGE_BYTES) /* 197632 */

#if HAS_TCG
// ---------------- tcgen05 / TMA helpers (arch-specific pass only) -----------
__device__ __forceinline__ uint32_t elect1(){
    uint32_t p;
    asm volatile("{\n\t.reg .pred p;\n\telect.sync _|p, 0xFFFFFFFF;\n\tselp.b32 %0, 1, 0, p;\n\t}" : "=r"(p));
    return p;
}
__device__ __forceinline__ uint32_t ctarank(){
    uint32_t r;
    asm("mov.u32 %0, %%cluster_ctarank;" : "=r"(r));
    return r;
}
// SW128 K-major descriptor: layout=2, version=1, SBO=64 (1024B = 8 rows x 128B), LBO=1
static constexpr uint64_t DESC_BASE_SW128 =
    (uint64_t(2) << 61) | (uint64_t(1) << 46) | (uint64_t(64) << 32) | (uint64_t(1) << 16);
#define MK128(a) (DESC_BASE_SW128 | ((uint64_t)((a) >> 4) & 0x3FFF))
// idesc: F32 accum (1<<4), TF32 a/b (2<<7 | 2<<10), N=256 (32<<17), M=128 (8<<24)
#define GEMM_IDESC 0x8400910u

__device__ __forceinline__ void mma_tf32_ss(uint32_t d, uint64_t a, uint64_t b, uint32_t en){
    asm volatile(
        "{\n\t.reg .pred p;\n\tsetp.ne.u32 p, %3, 0;\n\t"
        "tcgen05.mma.cta_group::1.kind::tf32 [%0], %1, %2, %4, {%5,%5,%5,%5}, p;\n\t}"
        :: "r"(d), "l"(a), "l"(b), "r"(en), "r"(GEMM_IDESC), "r"(0u) : "memory");
}
__device__ __forceinline__ void tc_commit(uint32_t mbar){
    asm volatile("tcgen05.commit.cta_group::1.mbarrier::arrive::one.shared::cluster.b64 [%0];"
                 :: "r"(mbar) : "memory");
}
__device__ __forceinline__ void tc_commit_mc(uint32_t mbar, uint16_t mask){
    asm volatile("tcgen05.commit.cta_group::1.mbarrier::arrive::one.shared::cluster.multicast::cluster.b64 [%0], %1;"
                 :: "r"(mbar), "h"(mask) : "memory");
}
__device__ __forceinline__ void mbar_init(uint32_t mbar, uint32_t cnt){
    asm volatile("mbarrier.init.shared.b64 [%0], %1;" :: "r"(mbar), "r"(cnt) : "memory");
}
__device__ __forceinline__ void mbar_wait(uint32_t mbar, uint32_t parity){
    asm volatile(
        "{\n\t.reg .pred P;\n\tWL_%=:\n\t"
        "mbarrier.try_wait.parity.acquire.cta.shared::cta.b64 P, [%0], %1, 0x989680;\n\t"
        "@P bra.uni WD_%=;\n\tbra.uni WL_%=;\n\tWD_%=:\n\t}"
        :: "r"(mbar), "r"(parity) : "memory");
}
__device__ __forceinline__ void mbar_wait_rlx(uint32_t mbar, uint32_t parity){
    asm volatile(
        "{\n\t.reg .pred P;\n\tWL_%=:\n\t"
        "mbarrier.try_wait.parity.relaxed.cta.shared::cta.b64 P, [%0], %1, 0x989680;\n\t"
        "@P bra.uni WD_%=;\n\tbra.uni WL_%=;\n\tWD_%=:\n\t}"
        :: "r"(mbar), "r"(parity) : "memory");
}
#define EXPECT_TX(mbar, bytes) \
    asm volatile("mbarrier.arrive.expect_tx.shared.b64 _, [%0], %1;" \
                 :: "r"(mbar), "r"((uint32_t)(bytes)) : "memory")
#define TMA2D(smem, map, x, y, mbar) \
    asm volatile("cp.async.bulk.tensor.2d.shared::cta.global.tile.mbarrier::complete_tx::bytes " \
                 "[%0], [%1, {%2, %3}], [%4];" \
                 :: "r"((uint32_t)(smem)), "l"(map), "r"((int)(x)), "r"((int)(y)), \
                    "r"((uint32_t)(mbar)) : "memory")
#define TMA2D_MC(smem, map, x, y, mbar, mask) \
    asm volatile("cp.async.bulk.tensor.2d.shared::cluster.global.tile.mbarrier::complete_tx::bytes.multicast::cluster " \
                 "[%0], [%1, {%2, %3}], [%4], %5;" \
                 :: "r"((uint32_t)(smem)), "l"(map), "r"((int)(x)), "r"((int)(y)), \
                    "r"((uint32_t)(mbar)), "h"((uint16_t)(mask)) : "memory")
#define CLUSTER_SYNC() do { \
    asm volatile("barrier.cluster.arrive.aligned;" ::: "memory"); \
    asm volatile("barrier.cluster.wait.aligned;" ::: "memory"); \
} while(0)

#define TC_FENCE_AFTER()  asm volatile("tcgen05.fence::after_thread_sync;" ::: "memory")
#define TC_FENCE_BEFORE() asm volatile("tcgen05.fence::before_thread_sync;" ::: "memory")
#define TC_WAIT_LD() asm volatile("tcgen05.wait::ld.sync.aligned;" ::: "memory")

#define LDTM32(r, addr) \
    asm volatile( \
        "tcgen05.ld.sync.aligned.32x32b.x32.b32 " \
        "{%0, %1, %2, %3, %4, %5, %6, %7, " \
        " %8, %9, %10, %11, %12, %13, %14, %15, " \
        " %16, %17, %18, %19, %20, %21, %22, %23, " \
        " %24, %25, %26, %27, %28, %29, %30, %31}, [%32];" \
        : "=r"((r)[0]),  "=r"((r)[1]),  "=r"((r)[2]),  "=r"((r)[3]), \
          "=r"((r)[4]),  "=r"((r)[5]),  "=r"((r)[6]),  "=r"((r)[7]), \
          "=r"((r)[8]),  "=r"((r)[9]),  "=r"((r)[10]), "=r"((r)[11]), \
          "=r"((r)[12]), "=r"((r)[13]), "=r"((r)[14]), "=r"((r)[15]), \
          "=r"((r)[16]), "=r"((r)[17]), "=r"((r)[18]), "=r"((r)[19]), \
          "=r"((r)[20]), "=r"((r)[21]), "=r"((r)[22]), "=r"((r)[23]), \
          "=r"((r)[24]), "=r"((r)[25]), "=r"((r)[26]), "=r"((r)[27]), \
          "=r"((r)[28]), "=r"((r)[29]), "=r"((r)[30]), "=r"((r)[31]) \
        : "r"(addr))
#endif  // HAS_TCG

// smem control offsets
#define MB_FULL(s)  (8  + (s)*8)     /* full[s]:  data ready (count 1 + tx) */
#define MB_EMPTY(s) (40 + (s)*8)     /* empty[s]: stage free (count 2)      */
#define MB_DONE     72               /* final MMA drain (count 1)           */

// ---------------------------------------------------------------------------
// Single-pass tf32 GEMM:  C[M,Ntot] = A[M,GK] * B^T  (B:[Ntot,GK] row-major)
// A,B fp32 pre-rounded to tf32. TMA (strided 2D, SW128) + B multicast pairs.
// ---------------------------------------------------------------------------
__global__ __launch_bounds__(256) __cluster_dims__(1, 2, 1)
void gemm_tf32(
    const CUtensorMap* __restrict__ tmaps,   // [A, B]
    const float* __restrict__ A, const float* __restrict__ B,
    float* __restrict__ C, int Ntot, const float* __restrict__ bias)
{
    const int tid = threadIdx.x;
    const int row0 = blockIdx.y * MT;
    const int col0 = blockIdx.x * NT;

#if HAS_TCG
    extern __shared__ char smem[];
    const uint32_t sbase = smem_u32(smem);
    const int wid = tid >> 5;
    const int lane = tid & 31;
    const uint32_t rank = ctarank();

    if (wid == 0) {
        asm volatile("tcgen05.alloc.cta_group::1.sync.aligned.shared::cta.b32 [%0], %1;"
                     :: "r"(sbase), "r"(512u) : "memory");
    }
    if (tid == 0) {
        #pragma unroll
        for (int s = 0; s < NSTAGE; s++) {
            mbar_init(sbase + MB_FULL(s), 1);    // producer's expect_tx arrival
            mbar_init(sbase + MB_EMPTY(s), 2);   // both CTAs' MMA commits
        }
        mbar_init(sbase + MB_DONE, 1);
    }
    __syncthreads();
    uint32_t tmem;
    asm volatile("ld.shared.b32 %0, [%1];" : "=r"(tmem) : "r"(sbase));
    if (wid == 0)
        asm volatile("tcgen05.relinquish_alloc_permit.cta_group::1.sync.aligned;");

    // all mbarriers must be visible cluster-wide before any multicast TMA
    CLUSTER_SYNC();

    uint32_t leader = 0, producer = 0;
    if (wid == 0) leader = elect1();
    if (wid == 1) producer = elect1();

    if (producer) {
        for (int ch = 0; ch < NCH; ch++) {
            const int st = ch % NSTAGE;
            const uint32_t sb = sbase + SM_TILE0 + st*STAGE_BYTES;
            if (ch >= NSTAGE)
                mbar_wait_rlx(sbase + MB_EMPTY(st), ((ch - NSTAGE) / NSTAGE) & 1);
            EXPECT_TX(sbase + MB_FULL(st), 65536u);
            TMA2D(sb + OA, tmaps + 0, ch*KCH, row0, sbase + MB_FULL(st));
            TMA2D_MC(sb + OB + rank*16384, tmaps + 1, ch*KCH,
                     col0 + (int)rank*128, sbase + MB_FULL(st), 3);
        }
    }

    if (leader) {
        uint32_t first = 0;
        const uint32_t tm0 = tmem, tm1 = tmem + 256;
        for (int ch = 0; ch < NCH; ch++) {
            const int st = ch % NSTAGE;
            mbar_wait(sbase + MB_FULL(st), (ch / NSTAGE) & 1);
            const uint32_t sb = sbase + SM_TILE0 + st*STAGE_BYTES;
            const uint64_t dA0 = MK128(sb + OA);
            const uint64_t dA1 = MK128(sb + OA + 16384);
            const uint64_t dB  = MK128(sb + OB);
            #pragma unroll
            for (int k = 0; k < 4; k++) {        // K=8 per tf32 MMA; 4 k-steps
                const uint64_t o = k*2;          // 32B per k-step
                mma_tf32_ss(tm0, dA0 + o, dB + o, first);
                mma_tf32_ss(tm1, dA1 + o, dB + o, first);
                first = 1;
            }
            tc_commit_mc(sbase + MB_EMPTY(st), 3);   // arm both CTAs' empty
        }
        tc_commit(sbase + MB_DONE);
    }

    // ---- all threads: wait for full MMA drain ----
    mbar_wait(sbase + MB_DONE, 0);
    TC_FENCE_AFTER();

    // ---- epilogue: warps 0-3 -> D0 rows, warps 4-7 -> D1 rows ----
    {
        const int mh = wid >> 2;
        const int r = row0 + mh*128 + (wid & 3)*32 + lane;
        const uint32_t tb = tmem + mh*256;
        float* crow = C + (size_t)r * Ntot;
        #pragma unroll
        for (int chk = 0; chk < 8; chk++) {
            uint32_t regs[32];
            LDTM32(regs, tb + chk*32);
            TC_WAIT_LD();
            const int c0 = col0 + chk*32;
            #pragma unroll
            for (int j = 0; j < 32; j += 4) {
                float4 v;
                v.x = __uint_as_float(regs[j+0]);
                v.y = __uint_as_float(regs[j+1]);
                v.z = __uint_as_float(regs[j+2]);
                v.w = __uint_as_float(regs[j+3]);
                if (bias) {
                    v.x += bias[c0+j+0]; v.y += bias[c0+j+1];
                    v.z += bias[c0+j+2]; v.w += bias[c0+j+3];
                }
                *(float4*)(crow + c0 + j) = v;
            }
        }
        TC_FENCE_BEFORE();
    }
    __syncthreads();
    if (tid == 0) {
        #pragma unroll
        for (int s = 0; s < NSTAGE; s++) {
            asm volatile("mbarrier.inval.shared.b64 [%0];" :: "r"(sbase + MB_FULL(s)) : "memory");
            asm volatile("mbarrier.inval.shared.b64 [%0];" :: "r"(sbase + MB_EMPTY(s)) : "memory");
        }
        asm volatile("mbarrier.inval.shared.b64 [%0];" :: "r"(sbase + MB_DONE) : "memory");
    }
    __syncthreads();
    if (wid == 0) {
        asm volatile("tcgen05.dealloc.cta_group::1.sync.aligned.b32 %0, %1;"
                     :: "r"(tmem), "r"(512u));
    }
    // no CTA may exit while peer multicast could target it
    CLUSTER_SYNC();

#else
    // ---- correctness-only fallback (dead code on sm_103a cubin) ----
    (void)tmaps;
    for (int idx = tid; idx < MT*NT; idx += 256) {
        const int r = row0 + idx / NT;
        const int c = col0 + idx % NT;
        float s = bias ? bias[c] : 0.f;
        for (int k = 0; k < GK; k++)
            s = fmaf(A[(size_t)r * GK + k], B[(size_t)c * GK + k], s);
        C[(size_t)r * Ntot + c] = s;
    }
#endif
}

// ---------------------------------------------------------------------------
// fp32 -> tf32-rounded fp32 (elementwise)
// ---------------------------------------------------------------------------
__global__ __launch_bounds__(256) void round_kernel(
    const float* __restrict__ in, float* __restrict__ outp, size_t n4)
{
    const size_t i = (size_t)blockIdx.x * blockDim.x + threadIdx.x;
    if (i >= n4) return;
    float4 v = ((const float4*)in)[i];
    v.x = rna_tf32(v.x); v.y = rna_tf32(v.y);
    v.z = rna_tf32(v.z); v.w = rna_tf32(v.w);
    ((float4*)outp)[i] = v;
}

// ---------------------------------------------------------------------------
// W [K,N] fp32 -> transposed tf32-rounded [N,K] row-major
// ---------------------------------------------------------------------------
__global__ __launch_bounds__(256) void transpose_round(
    const float* __restrict__ W, float* __restrict__ o, int K, int N)
{
    __shared__ float t[32][33];
    const int n0 = blockIdx.x * 32, k0 = blockIdx.y * 32;
    const int tx = threadIdx.x & 31, ty = threadIdx.x >> 5;
    #pragma unroll
    for (int i = ty; i < 32; i += 8)
        t[i][tx] = W[(size_t)(k0 + i) * N + n0 + tx];
    __syncthreads();
    #pragma unroll
    for (int i = ty; i < 32; i += 8)
        o[(size_t)(n0 + i) * K + k0 + tx] = rna_tf32(t[tx][i]);
}

// ---------------------------------------------------------------------------
// attn part 1: raw cross-cov partials + ssq partials over an N-slice of 512.
// ---------------------------------------------------------------------------
__global__ __launch_bounds__(256) void attn_part(void)
{
    const int bh = blockIdx.x;
    const int sl = blockIdx.y;
    const int b  = bh / Hh, h = bh % Hh;
    const int tid = threadIdx.x;
    const int tx = tid & 15, ty = tid >> 4;

    __shared__ float Qs[64][68];
    __shared__ float Ks[64][68];
    __shared__ float ps[256];

    const size_t rowbase = (size_t)b * Nn + sl * (Nn / NSPLIT);
    const int qoff = h * dh;
    const int koff = Dd + h * dh;

    float acc[4][4];
    #pragma unroll
    for (int i = 0; i < 4; i++)
        #pragma unroll
        for (int j = 0; j < 4; j++) acc[i][j] = 0.f;
    float pssq = 0.f;

    const int lr = tid >> 4;
    const int lc = (tid & 15) << 2;
    const int scol  = tid & 127;
    const int shalf = (tid >> 7) * 32;

    for (int n0 = 0; n0 < Nn / NSPLIT; n0 += 64) {
        #pragma unroll
        for (int pp = 0; pp < 64; pp += 16) {
            const size_t grow = (rowbase + n0 + pp + lr) * QKVC;
            *(float4*)&Qs[pp + lr][lc] = *(const float4*)(g_qkv + grow + qoff + lc);
            *(float4*)&Ks[pp + lr][lc] = *(const float4*)(g_qkv + grow + koff + lc);
        }
        __syncthreads();
        #pragma unroll 4
        for (int n = 0; n < 64; n++) {
            float rq[4], rk[4];
            *(float4*)rq = *(const float4*)&Qs[n][tx * 4];
            *(float4*)rk = *(const float4*)&Ks[n][ty * 4];
            #pragma unroll
            for (int i = 0; i < 4; i++)
                #pragma unroll
                for (int j = 0; j < 4; j++)
                    acc[i][j] = fmaf(rk[i], rq[j], acc[i][j]);
        }
        {
            const float* colp = (scol < 64) ? &Qs[0][scol] : &Ks[0][scol - 64];
            #pragma unroll
            for (int n = 0; n < 32; n++) {
                const float v = colp[(size_t)(shalf + n) * 68];
                pssq = fmaf(v, v, pssq);
            }
        }
        __syncthreads();
    }

    ps[tid] = pssq;
    __syncthreads();
    if (tid < 128)
        g_psq[(bh * NSPLIT + sl) * 128 + tid] = ps[tid] + ps[tid + 128];

    float* op = g_part + (size_t)(bh * NSPLIT + sl) * 4096;
    #pragma unroll
    for (int i = 0; i < 4; i++)
        #pragma unroll
        for (int j = 0; j < 4; j++)
            op[(ty * 4 + i) * 64 + tx * 4 + j] = acc[i][j];
}

// ---------------------------------------------------------------------------
// attn part 2: reduce partials, norms, temperature, softmax. grid 96.
// ---------------------------------------------------------------------------
__global__ __launch_bounds__(256) void attn_final(const float* __restrict__ temp)
{
    const int bh = blockIdx.x;
    const int h  = bh % Hh;
    const int tid = threadIdx.x;

    __shared__ float Qs[64][65];
    __shared__ float normQ[64], normK[64];

    if (tid < 128) {
        float s = 0.f;
        #pragma unroll
        for (int sl = 0; sl < NSPLIT; sl++)
            s += g_psq[(bh * NSPLIT + sl) * 128 + tid];
        const float nv = fmaxf(sqrtf(s), 1e-12f);
        if (tid < 64) normQ[tid] = nv; else normK[tid - 64] = nv;
    }
    __syncthreads();

    const float tv = temp[h];
    const float* pp = g_part + (size_t)bh * NSPLIT * 4096;
    #pragma unroll
    for (int e = 0; e < 16; e++) {
        const int idx = e * 256 + tid;
        float s = 0.f;
        #pragma unroll
        for (int sl = 0; sl < NSPLIT; sl++)
            s += pp[sl * 4096 + idx];
        const int p = idx >> 6, q = idx & 63;
        Qs[p][q] = s * tv / (normK[p] * normQ[q]);
    }
    __syncthreads();

    if (tid < 64) {
        const int p = tid;
        float m = -1e30f;
        for (int q = 0; q < 64; q++) m = fmaxf(m, Qs[p][q]);
        float s = 0.f;
        for (int q = 0; q < 64; q++) s += expf(Qs[p][q] - m);
        const float inv = 1.f / s;
        float* op = g_attn + (size_t)bh * 4096 + p * 64;
        for (int q = 0; q < 64; q++) op[q] = expf(Qs[p][q] - m) * inv;
    }
}

// ---------------------------------------------------------------------------
// out[b,h,n,q] = sum_p v[n,p] attn[p,q]  -> tf32-rounded fp32, row-major
// ---------------------------------------------------------------------------
__global__ __launch_bounds__(256) void av_kernel()
{
    const int bh = blockIdx.x;
    const int nt = blockIdx.y;
    const int b  = bh / Hh, h = bh % Hh;
    const int tid = threadIdx.x;
    const int tx = tid & 15, ty = tid >> 4;

    __shared__ float At[64][68];
    __shared__ float Vs[64][68];

    {
        const float* ap = g_attn + (size_t)bh * 4096;
        #pragma unroll
        for (int pp = 0; pp < 4; pp++) {
            const int idx = pp * 1024 + tid * 4;
            *(float4*)&At[idx >> 6][idx & 63] = *(const float4*)(ap + idx);
        }
    }
    const int lr = tid >> 4, lc = (tid & 15) << 2;
    const int voff = 2 * Dd + h * dh;
    const size_t rowbase = (size_t)b * Nn + nt * 64;
    #pragma unroll
    for (int pp = 0; pp < 64; pp += 16)
        *(float4*)&Vs[pp + lr][lc] =
            *(const float4*)(g_qkv + (rowbase + pp + lr) * QKVC + voff + lc);
    __syncthreads();

    float acc[4][4];
    #pragma unroll
    for (int i = 0; i < 4; i++)
        #pragma unroll
        for (int j = 0; j < 4; j++) acc[i][j] = 0.f;

    #pragma unroll 8
    for (int p = 0; p < 64; p++) {
        float ra[4];
        *(float4*)ra = *(const float4*)&At[p][tx * 4];
        float rv[4];
        #pragma unroll
        for (int i = 0; i < 4; i++) rv[i] = Vs[ty * 4 + i][p];
        #pragma unroll
        for (int i = 0; i < 4; i++)
            #pragma unroll
            for (int j = 0; j < 4; j++)
                acc[i][j] = fmaf(rv[i], ra[j], acc[i][j]);
    }

    #pragma unroll
    for (int i = 0; i < 4; i++) {
        const size_t r = rowbase + ty * 4 + i;
        float4 v;
        v.x = rna_tf32(acc[i][0]); v.y = rna_tf32(acc[i][1]);
        v.z = rna_tf32(acc[i][2]); v.w = rna_tf32(acc[i][3]);
        *(float4*)(g_oattn + r * Dd + h * dh + tx * 4) = v;
    }
}

// ---------------------------------------------------------------------------
// host: tensormap construction via driver entry point (no -lcuda needed)
// ---------------------------------------------------------------------------
typedef CUresult (*EncodeTiledFn)(
    CUtensorMap*, CUtensorMapDataType, cuuint32_t, void*,
    const cuuint64_t*, const cuuint64_t*, const cuuint32_t*, const cuuint32_t*,
    CUtensorMapInterleave, CUtensorMapSwizzle, CUtensorMapL2promotion,
    CUtensorMapFloatOOBfill);

static void encode_map(EncodeTiledFn enc, CUtensorMap* m, void* base,
                       unsigned long long nrows, unsigned boxrows)
{
    cuuint64_t dims[2]    = {(cuuint64_t)GK, nrows};   // [768 elems, nrows]
    cuuint64_t strides[1] = {(cuuint64_t)GK * 4};      // 3072 bytes per row
    cuuint32_t box[2]     = {32u, boxrows};            // 128B x boxrows
    cuuint32_t estr[2]    = {1u, 1u};
    enc(m, CU_TENSOR_MAP_DATA_TYPE_FLOAT32, 2, base, dims, strides, box, estr,
        CU_TENSOR_MAP_INTERLEAVE_NONE, CU_TENSOR_MAP_SWIZZLE_128B,
        CU_TENSOR_MAP_L2_PROMOTION_L2_128B, CU_TENSOR_MAP_FLOAT_OOB_FILL_NONE);
}

extern "C" void kernel_launch(void* const* d_in, const int* in_sizes, int n_in,
                              void* d_out, int out_size)
{
    const float* x     = (const float*)d_in[0];
    const float* Wqkv  = (const float*)d_in[1];
    const float* temp  = (const float*)d_in[2];
    const float* Wout  = (const float*)d_in[3];
    const float* bout  = (const float*)d_in[4];
    float* out = (float*)d_out;

    float *qkv, *xt, *wt, *wot, *oattn;
    cudaGetSymbolAddress((void**)&qkv,   g_qkv);
    cudaGetSymbolAddress((void**)&xt,    g_xt);
    cudaGetSymbolAddress((void**)&wt,    g_wt);
    cudaGetSymbolAddress((void**)&wot,   g_wot);
    cudaGetSymbolAddress((void**)&oattn, g_oattn);
    CUtensorMap* dmaps;
    cudaGetSymbolAddress((void**)&dmaps, g_tmaps);

    // build tensormaps (static host buffer persists for graph replays)
    static CUtensorMap h_tmaps[4];
    static EncodeTiledFn enc = nullptr;
    if (!enc) {
        void* p = nullptr;
        cudaDriverEntryPointQueryResult st;
        cudaGetDriverEntryPoint("cuTensorMapEncodeTiled", &p, cudaEnableDefault, &st);
        enc = (EncodeTiledFn)p;
    }
    encode_map(enc, &h_tmaps[0], xt,    (unsigned long long)Mrows, 256);
    encode_map(enc, &h_tmaps[1], wt,    (unsigned long long)QKVC,  128);
    encode_map(enc, &h_tmaps[2], oattn, (unsigned long long)Mrows, 256);
    encode_map(enc, &h_tmaps[3], wot,   (unsigned long long)Dd,    128);
    cudaMemcpyToSymbolAsync(g_tmaps, h_tmaps, sizeof(h_tmaps), 0,
                            cudaMemcpyHostToDevice, 0);

    cudaFuncSetAttribute(gemm_tf32, cudaFuncAttributeMaxDynamicSharedMemorySize, GEMM_SMEM);

    // 1) round x to tf32; transpose+round weights
    {
        size_t n4 = (size_t)Mrows * Dd / 4;
        round_kernel<<<(unsigned)((n4 + 255) / 256), 256>>>(x, xt, n4);
    }
    transpose_round<<<dim3(QKVC/32, Dd/32), 256>>>(Wqkv, wt, Dd, QKVC);
    transpose_round<<<dim3(Dd/32,  Dd/32), 256>>>(Wout, wot, Dd, Dd);

    // 2) qkv = x @ Wqkv  (tcgen05 tf32, TMA + B-multicast)
    gemm_tf32<<<dim3(QKVC/NT, Mrows/MT), 256, GEMM_SMEM>>>(
        dmaps + 0, xt, wt, qkv, QKVC, nullptr);

    // 3) fused normalize + cross-covariance + temperature + softmax (split 8x)
    attn_part<<<dim3(Bc * Hh, NSPLIT), 256>>>();
    attn_final<<<dim3(Bc * Hh), 256>>>(temp);

    // 4) out = v @ attn  (writes tf32-rounded fp32)
    av_kernel<<<dim3(Bc * Hh, Nn / 64), 256>>>();

    // 5) final projection + bias (tcgen05 tf32)
    gemm_tf32<<<dim3(Dd/NT, Mrows/MT), 256, GEMM_SMEM>>>(
        dmaps + 2, oattn, wot, out, Dd, bout);
}